// round 12
// baseline (speedup 1.0000x reference)
#include <cuda_runtime.h>
#include <cuda_fp16.h>
#include <math.h>
#include <stdint.h>

#define NTOK 4096
#define DIM  1024
#define HID  2048
#define NE   8

// ---------------------------------------------------------------------------
// Helpers
// ---------------------------------------------------------------------------
__device__ __forceinline__ uint32_t smem_to_u32(const void* p) {
    uint32_t a;
    asm("{ .reg .u64 t; cvta.to.shared.u64 t, %1; cvt.u32.u64 %0, t; }"
        : "=r"(a) : "l"(p));
    return a;
}

#define SWZ(rel) ((rel) ^ (((rel) >> 3) & 0x70))   // 128B-row swizzle

#define CP_ASYNC(dst, src, sz) \
    asm volatile("cp.async.cg.shared.global [%0], [%1], 16, %2;" \
        :: "r"(dst), "l"(src), "r"(sz))
#define CP_COMMIT() asm volatile("cp.async.commit_group;")
#define CP_WAIT(N)  asm volatile("cp.async.wait_group %0;" :: "n"(N))

__device__ __forceinline__ void ldsm_x4(uint32_t addr, uint32_t* r) {
    asm volatile("ldmatrix.sync.aligned.m8n8.x4.shared.b16 {%0,%1,%2,%3}, [%4];"
        : "=r"(r[0]), "=r"(r[1]), "=r"(r[2]), "=r"(r[3]) : "r"(addr));
}
__device__ __forceinline__ void ldsm_x4_t(uint32_t addr, uint32_t* r) {
    asm volatile("ldmatrix.sync.aligned.m8n8.x4.trans.shared.b16 {%0,%1,%2,%3}, [%4];"
        : "=r"(r[0]), "=r"(r[1]), "=r"(r[2]), "=r"(r[3]) : "r"(addr));
}
__device__ __forceinline__ void mma_f16(float* d, const uint32_t* a, const uint32_t* b) {
    asm volatile(
        "mma.sync.aligned.m16n8k16.row.col.f32.f16.f16.f32 "
        "{%0,%1,%2,%3}, {%4,%5,%6,%7}, {%8,%9}, {%0,%1,%2,%3};"
        : "+f"(d[0]), "+f"(d[1]), "+f"(d[2]), "+f"(d[3])
        : "r"(a[0]), "r"(a[1]), "r"(a[2]), "r"(a[3]), "r"(b[0]), "r"(b[1]));
}

__device__ __forceinline__ uint32_t pack2(__half a, __half b) {
    __half2 t = __halves2half2(a, b);
    uint32_t r; memcpy(&r, &t, 4); return r;
}
__device__ __forceinline__ uint2 cvt4h(float4 f) {
    uint2 hv;
    hv.x = pack2(__float2half_rn(f.x), __float2half_rn(f.y));
    hv.y = pack2(__float2half_rn(f.z), __float2half_rn(f.w));
    return hv;
}

// ---------------------------------------------------------------------------
// Scratch (device globals)
// ---------------------------------------------------------------------------
__device__ int   g_counts[NE];
__device__ int   g_tok[NE * NTOK];
__device__ float g_wt[NE * NTOK];
__device__ __half g_x[(size_t)NTOK * DIM];
__device__ __half g_w1[(size_t)NE * DIM * HID];
__device__ __half g_w3[(size_t)NE * DIM * HID];
__device__ __half g_w2[(size_t)NE * HID * DIM];
__device__ __half g_h[(size_t)(2 * NTOK) * HID];

// ---------------------------------------------------------------------------
// K0: prep — weights fp32 -> fp16 + zero out + zero counts
// ---------------------------------------------------------------------------
__global__ void prep_kernel(const float4* __restrict__ W1,
                            const float4* __restrict__ W3,
                            const float4* __restrict__ W2,
                            float4* __restrict__ out, int n4) {
    const int n8   = NE * DIM * HID / 8;
    const int gper = gridDim.x / 3;
    int t  = blockIdx.x / gper;
    int bl = blockIdx.x % gper;
    const float4* s = (t == 0) ? W1 : ((t == 1) ? W3 : W2);
    __half* d = (t == 0) ? g_w1 : ((t == 1) ? g_w3 : g_w2);
    for (int i = bl * blockDim.x + threadIdx.x; i < n8; i += gper * blockDim.x) {
        float4 a = s[2 * i], b = s[2 * i + 1];
        uint2 ha = cvt4h(a), hb = cvt4h(b);
        *(uint4*)(d + (size_t)i * 8) = make_uint4(ha.x, ha.y, hb.x, hb.y);
    }
    int gid = blockIdx.x * blockDim.x + threadIdx.x;
    if (gid < NE) g_counts[gid] = 0;
    float4 z = make_float4(0.f, 0.f, 0.f, 0.f);
    for (int i = gid; i < n4; i += gridDim.x * blockDim.x) out[i] = z;
}

// ---------------------------------------------------------------------------
// K1: routing + x fp16 conversion fused (one warp/token)
// ---------------------------------------------------------------------------
__global__ void route_kernel(const float4* __restrict__ x4,
                             const float* __restrict__ Wg) {
    int warp = (blockIdx.x * blockDim.x + threadIdx.x) >> 5;
    int lane = threadIdx.x & 31;
    if (warp >= NTOK) return;

    float sc[NE];
#pragma unroll
    for (int e = 0; e < NE; e++) sc[e] = 0.f;

#pragma unroll
    for (int j = 0; j < 8; j++) {
        int i4 = j * 32 + lane;
        float4 xv = x4[(size_t)warp * (DIM / 4) + i4];
        *(uint2*)(g_x + (size_t)warp * DIM + i4 * 4) = cvt4h(xv);
        float xs[4] = {xv.x, xv.y, xv.z, xv.w};
#pragma unroll
        for (int c = 0; c < 4; c++) {
            int row = i4 * 4 + c;
#pragma unroll
            for (int e = 0; e < NE; e++)
                sc[e] += xs[c] * Wg[row * NE + e];
        }
    }
#pragma unroll
    for (int o = 16; o > 0; o >>= 1)
#pragma unroll
        for (int e = 0; e < NE; e++)
            sc[e] += __shfl_xor_sync(0xffffffffu, sc[e], o);

    if (lane == 0) {
        int i0 = 0; float s0 = sc[0];
#pragma unroll
        for (int e = 1; e < NE; e++) if (sc[e] > s0) { s0 = sc[e]; i0 = e; }
        int i1 = -1; float s1 = -INFINITY;
#pragma unroll
        for (int e = 0; e < NE; e++)
            if (e != i0 && sc[e] > s1) { s1 = sc[e]; i1 = e; }
        float e1  = expf(s1 - s0);
        float inv = 1.f / (1.f + e1);
        int p0 = atomicAdd(&g_counts[i0], 1);
        g_tok[i0 * NTOK + p0] = warp;
        g_wt [i0 * NTOK + p0] = inv;
        int p1 = atomicAdd(&g_counts[i1], 1);
        g_tok[i1 * NTOK + p1] = warp;
        g_wt [i1 * NTOK + p1] = e1 * inv;
    }
}

__device__ __forceinline__ int expert_base(int e) {
    int b = 0;
#pragma unroll
    for (int j = 0; j < NE; j++) if (j < e) b += g_counts[j];
    return b;
}

// ---------------------------------------------------------------------------
// K3: FFN1 — fp16 single-pass, BK=64. BM=128, BN=64, 128 thr (4 warps 2m x 2n,
// warp tile 64x32). Stage 32KB x3 = 96KB; 2 CTAs/SM.
// Loop: wait(1) -> barrier -> mma(it, 4 ks) -> load(it+2) -> commit.
// ---------------------------------------------------------------------------
#define F1_STAGE 32768
#define F2_STAGE 24576

__global__ __launch_bounds__(128, 2) void ffn1_kernel() {
    extern __shared__ char sm[];
    __shared__ int s_tok[128];

    int e   = blockIdx.z;
    int cnt = g_counts[e];
    int m0  = blockIdx.y * 128;
    if (m0 >= cnt) return;
    int n0   = blockIdx.x * 64;
    int base = expert_base(e);

    int tid = threadIdx.x, wid = tid >> 5, l = tid & 31;
    int mw = (wid >> 1) * 64, nw = (wid & 1) * 32;

    {
        int mg = m0 + tid;
        s_tok[tid] = (mg < cnt) ? g_tok[e * NTOK + mg] : -1;
    }
    __syncthreads();

    uint32_t sbase = smem_to_u32(sm);
    size_t eoffW = (size_t)e * DIM * HID;

    auto load_tile = [&](int it, int b) {
        int kb = it * 64;
        uint32_t abase = sbase + b * F1_STAGE;
        uint32_t bbase = abase + 16384;
        // A: 1024 chunks of 16B (128 rows x 8)
#pragma unroll
        for (int j = 0; j < 8; j++) {
            int c = tid + j * 128;
            int row = c >> 3, cc = c & 7;
            int tok = s_tok[row];
            const void* src = g_x + ((size_t)(tok < 0 ? 0 : tok) * DIM + kb + cc * 8);
            uint32_t dst = abase + SWZ((uint32_t)(row * 128 + cc * 16));
            int sz = (tok < 0) ? 0 : 16;
            CP_ASYNC(dst, src, sz);
        }
        // B: 1024 chunks over 2 planes (W1, W3), 64k x 64n each
#pragma unroll
        for (int j = 0; j < 8; j++) {
            int c = tid + j * 128;
            int p = c >> 9, w = c & 511;
            int kr = w >> 3, n = (w & 7) * 8;
            const __half* sp = p ? g_w3 : g_w1;
            const void* src = sp + (eoffW + (size_t)(kb + kr) * HID + n0 + n);
            uint32_t dst = bbase + p * 8192 + SWZ((uint32_t)(kr * 128 + n * 2));
            CP_ASYNC(dst, src, 16);
        }
    };

    float acc1[4][4][4] = {};
    float acc3[4][4][4] = {};

    const int NIT = DIM / 64;
    load_tile(0, 0); CP_COMMIT();
    load_tile(1, 1); CP_COMMIT();

    for (int it = 0; it < NIT; it++) {
        CP_WAIT(1);
        __syncthreads();

        uint32_t aB = sbase + (it % 3) * F1_STAGE;
        uint32_t bB = aB + 16384;
        uint32_t b1 = bB, b3 = bB + 8192;

#pragma unroll
        for (int ks = 0; ks < 4; ks++) {
            uint32_t a[4][4];
#pragma unroll
            for (int mt = 0; mt < 4; mt++) {
                int row  = mw + mt * 16 + ((l >> 3) & 1) * 8 + (l & 7);
                int kbyt = ks * 32 + (l >> 4) * 16;
                ldsm_x4(aB + SWZ((uint32_t)(row * 128 + kbyt)), a[mt]);
            }
            int krow = ks * 16 + ((l >> 3) & 1) * 8 + (l & 7);
            uint32_t rb0 = krow * 128 + (nw + (l >> 4) * 8) * 2;
            uint32_t rb1 = rb0 + 32;
            uint32_t s0 = SWZ(rb0), s1 = SWZ(rb1);

            {   // W1
                uint32_t bh[8];
                ldsm_x4_t(b1 + s0, bh); ldsm_x4_t(b1 + s1, bh + 4);
#pragma unroll
                for (int mt = 0; mt < 4; mt++)
#pragma unroll
                    for (int nj = 0; nj < 4; nj++)
                        mma_f16(acc1[mt][nj], a[mt], &bh[nj * 2]);
            }
            {   // W3
                uint32_t bh[8];
                ldsm_x4_t(b3 + s0, bh); ldsm_x4_t(b3 + s1, bh + 4);
#pragma unroll
                for (int mt = 0; mt < 4; mt++)
#pragma unroll
                    for (int nj = 0; nj < 4; nj++)
                        mma_f16(acc3[mt][nj], a[mt], &bh[nj * 2]);
            }
        }

        if (it + 2 < NIT) load_tile(it + 2, (it + 2) % 3);
        CP_COMMIT();
    }

    // ---- epilogue: SwiGLU -> g_h (fp16) ----
#pragma unroll
    for (int mt = 0; mt < 4; mt++) {
#pragma unroll
        for (int hf = 0; hf < 2; hf++) {
            int row = m0 + mw + mt * 16 + (l >> 2) + hf * 8;
            if (row < cnt) {
                size_t rb = (size_t)(base + row) * HID + n0 + nw;
#pragma unroll
                for (int nj = 0; nj < 4; nj++) {
                    float a0 = acc1[mt][nj][hf * 2 + 0];
                    float a1 = acc1[mt][nj][hf * 2 + 1];
                    float h0 = a0 / (1.f + __expf(-a0)) * acc3[mt][nj][hf * 2 + 0];
                    float h1 = a1 / (1.f + __expf(-a1)) * acc3[mt][nj][hf * 2 + 1];
                    int c = nj * 8 + (l & 3) * 2;
                    *(uint32_t*)(g_h + rb + c) =
                        pack2(__float2half_rn(h0), __float2half_rn(h1));
                }
            }
        }
    }
}

// ---------------------------------------------------------------------------
// K4: FFN2 — fp16 single-pass, BK=64. BM=128, BN=64, 128 thr (4 warps 2m x 2n,
// warp tile 64x32). Stage 24KB x3 = 72KB; 3 CTAs/SM.
// ---------------------------------------------------------------------------
__global__ __launch_bounds__(128, 3) void ffn2_kernel(float* __restrict__ out) {
    extern __shared__ char sm[];

    int e   = blockIdx.z;
    int cnt = g_counts[e];
    int m0  = blockIdx.y * 128;
    if (m0 >= cnt) return;
    int n0   = blockIdx.x * 64;
    int base = expert_base(e);

    int tid = threadIdx.x, wid = tid >> 5, l = tid & 31;
    int mw = (wid >> 1) * 64, nw = (wid & 1) * 32;

    uint32_t sbase = smem_to_u32(sm);
    size_t eoffW = (size_t)e * HID * DIM;

    auto load_tile = [&](int it, int b) {
        int kb = it * 64;
        uint32_t abase = sbase + b * F2_STAGE;
        uint32_t bbase = abase + 16384;
#pragma unroll
        for (int j = 0; j < 8; j++) {
            int c = tid + j * 128;
            int row = c >> 3, cc = c & 7;
            int mg = m0 + row;
            bool v = mg < cnt;
            const void* src = g_h + ((size_t)(v ? base + mg : 0) * HID + kb + cc * 8);
            uint32_t dst = abase + SWZ((uint32_t)(row * 128 + cc * 16));
            int sz = v ? 16 : 0;
            CP_ASYNC(dst, src, sz);
        }
#pragma unroll
        for (int j = 0; j < 4; j++) {
            int c = tid + j * 128;
            int kr = c >> 3, n = (c & 7) * 8;
            const void* src = g_w2 + (eoffW + (size_t)(kb + kr) * DIM + n0 + n);
            uint32_t dst = bbase + SWZ((uint32_t)(kr * 128 + n * 2));
            CP_ASYNC(dst, src, 16);
        }
    };

    float acc[4][4][4] = {};

    const int NIT = HID / 64;
    load_tile(0, 0); CP_COMMIT();
    load_tile(1, 1); CP_COMMIT();

    for (int it = 0; it < NIT; it++) {
        CP_WAIT(1);
        __syncthreads();

        uint32_t aB = sbase + (it % 3) * F2_STAGE;
        uint32_t bB = aB + 16384;

#pragma unroll
        for (int ks = 0; ks < 4; ks++) {
            uint32_t a[4][4];
#pragma unroll
            for (int mt = 0; mt < 4; mt++) {
                int row  = mw + mt * 16 + ((l >> 3) & 1) * 8 + (l & 7);
                int kbyt = ks * 32 + (l >> 4) * 16;
                ldsm_x4(aB + SWZ((uint32_t)(row * 128 + kbyt)), a[mt]);
            }
            int krow = ks * 16 + ((l >> 3) & 1) * 8 + (l & 7);
            uint32_t rb0 = krow * 128 + (nw + (l >> 4) * 8) * 2;
            uint32_t rb1 = rb0 + 32;
            uint32_t s0 = SWZ(rb0), s1 = SWZ(rb1);

            uint32_t bh[8];
            ldsm_x4_t(bB + s0, bh); ldsm_x4_t(bB + s1, bh + 4);
#pragma unroll
            for (int mt = 0; mt < 4; mt++)
#pragma unroll
                for (int nj = 0; nj < 4; nj++)
                    mma_f16(acc[mt][nj], a[mt], &bh[nj * 2]);
        }

        if (it + 2 < NIT) load_tile(it + 2, (it + 2) % 3);
        CP_COMMIT();
    }

    // ---- epilogue: out[tok] += w * acc ----
#pragma unroll
    for (int mt = 0; mt < 4; mt++) {
#pragma unroll
        for (int hf = 0; hf < 2; hf++) {
            int row = m0 + mw + mt * 16 + (l >> 2) + hf * 8;
            if (row < cnt) {
                int   tok = g_tok[e * NTOK + row];
                float w   = g_wt [e * NTOK + row];
                float* orow = out + (size_t)tok * DIM + n0 + nw;
#pragma unroll
                for (int nj = 0; nj < 4; nj++) {
                    int c = nj * 8 + (l & 3) * 2;
                    atomicAdd(&orow[c],     w * acc[mt][nj][hf * 2 + 0]);
                    atomicAdd(&orow[c + 1], w * acc[mt][nj][hf * 2 + 1]);
                }
            }
        }
    }
}

// ---------------------------------------------------------------------------
// Launch
// ---------------------------------------------------------------------------
extern "C" void kernel_launch(void* const* d_in, const int* in_sizes, int n_in,
                              void* d_out, int out_size) {
    const float* x  = (const float*)d_in[0];
    const float* Wg = (const float*)d_in[1];
    const float* W1 = (const float*)d_in[2];
    const float* W3 = (const float*)d_in[3];
    const float* W2 = (const float*)d_in[4];
    float* out = (float*)d_out;

    cudaFuncSetAttribute(ffn1_kernel,
        cudaFuncAttributeMaxDynamicSharedMemorySize, 3 * F1_STAGE);
    cudaFuncSetAttribute(ffn2_kernel,
        cudaFuncAttributeMaxDynamicSharedMemorySize, 3 * F2_STAGE);

    prep_kernel<<<3 * 1024, 512>>>((const float4*)W1, (const float4*)W3,
                                   (const float4*)W2, (float4*)out,
                                   out_size / 4);
    route_kernel<<<NTOK / 8, 256>>>((const float4*)x, Wg);

    dim3 g1(HID / 64, NTOK / 128, NE);    // 32 x 32 x 8
    ffn1_kernel<<<g1, 128, 3 * F1_STAGE>>>();

    dim3 g2(DIM / 64, NTOK / 128, NE);    // 16 x 32 x 8
    ffn2_kernel<<<g2, 128, 3 * F2_STAGE>>>(out);
}

// round 13
// speedup vs baseline: 1.0371x; 1.0371x over previous
#include <cuda_runtime.h>
#include <cuda_fp16.h>
#include <math.h>
#include <stdint.h>

#define NTOK 4096
#define DIM  1024
#define HID  2048
#define NE   8

// ---------------------------------------------------------------------------
// Helpers
// ---------------------------------------------------------------------------
__device__ __forceinline__ uint32_t smem_to_u32(const void* p) {
    uint32_t a;
    asm("{ .reg .u64 t; cvta.to.shared.u64 t, %1; cvt.u32.u64 %0, t; }"
        : "=r"(a) : "l"(p));
    return a;
}

#define SWZ(rel) ((rel) ^ (((rel) >> 3) & 0x70))   // 128B-row swizzle

#define CP_ASYNC(dst, src, sz) \
    asm volatile("cp.async.cg.shared.global [%0], [%1], 16, %2;" \
        :: "r"(dst), "l"(src), "r"(sz))
#define CP_COMMIT() asm volatile("cp.async.commit_group;")
#define CP_WAIT(N)  asm volatile("cp.async.wait_group %0;" :: "n"(N))

__device__ __forceinline__ void ldsm_x4(uint32_t addr, uint32_t* r) {
    asm volatile("ldmatrix.sync.aligned.m8n8.x4.shared.b16 {%0,%1,%2,%3}, [%4];"
        : "=r"(r[0]), "=r"(r[1]), "=r"(r[2]), "=r"(r[3]) : "r"(addr));
}
__device__ __forceinline__ void ldsm_x4_t(uint32_t addr, uint32_t* r) {
    asm volatile("ldmatrix.sync.aligned.m8n8.x4.trans.shared.b16 {%0,%1,%2,%3}, [%4];"
        : "=r"(r[0]), "=r"(r[1]), "=r"(r[2]), "=r"(r[3]) : "r"(addr));
}
__device__ __forceinline__ void mma_f16(float* d, const uint32_t* a, const uint32_t* b) {
    asm volatile(
        "mma.sync.aligned.m16n8k16.row.col.f32.f16.f16.f32 "
        "{%0,%1,%2,%3}, {%4,%5,%6,%7}, {%8,%9}, {%0,%1,%2,%3};"
        : "+f"(d[0]), "+f"(d[1]), "+f"(d[2]), "+f"(d[3])
        : "r"(a[0]), "r"(a[1]), "r"(a[2]), "r"(a[3]), "r"(b[0]), "r"(b[1]));
}

__device__ __forceinline__ uint32_t pack2(__half a, __half b) {
    __half2 t = __halves2half2(a, b);
    uint32_t r; memcpy(&r, &t, 4); return r;
}
__device__ __forceinline__ uint2 cvt4h(float4 f) {
    uint2 hv;
    hv.x = pack2(__float2half_rn(f.x), __float2half_rn(f.y));
    hv.y = pack2(__float2half_rn(f.z), __float2half_rn(f.w));
    return hv;
}

// ---------------------------------------------------------------------------
// Scratch (device globals)
// ---------------------------------------------------------------------------
__device__ int   g_counts[NE];
__device__ int   g_tok[NE * NTOK];
__device__ float g_wt[NE * NTOK];
__device__ __half g_x[(size_t)NTOK * DIM];
__device__ __half g_w1[(size_t)NE * DIM * HID];
__device__ __half g_w3[(size_t)NE * DIM * HID];
__device__ __half g_w2[(size_t)NE * HID * DIM];
__device__ __half g_h[(size_t)(2 * NTOK) * HID];

// ---------------------------------------------------------------------------
// K0: prep — weights fp32 -> fp16 (streaming loads) + zero out + zero counts
// ---------------------------------------------------------------------------
__global__ void prep_kernel(const float4* __restrict__ W1,
                            const float4* __restrict__ W3,
                            const float4* __restrict__ W2,
                            float4* __restrict__ out, int n4) {
    const int n8   = NE * DIM * HID / 8;
    const int gper = gridDim.x / 3;
    int t  = blockIdx.x / gper;
    int bl = blockIdx.x % gper;
    const float4* s = (t == 0) ? W1 : ((t == 1) ? W3 : W2);
    __half* d = (t == 0) ? g_w1 : ((t == 1) ? g_w3 : g_w2);
    for (int i = bl * blockDim.x + threadIdx.x; i < n8; i += gper * blockDim.x) {
        float4 a = __ldcs(&s[2 * i]);          // evict-first: fp32 read once
        float4 b = __ldcs(&s[2 * i + 1]);
        uint2 ha = cvt4h(a), hb = cvt4h(b);
        *(uint4*)(d + (size_t)i * 8) = make_uint4(ha.x, ha.y, hb.x, hb.y);
    }
    int gid = blockIdx.x * blockDim.x + threadIdx.x;
    if (gid < NE) g_counts[gid] = 0;
    float4 z = make_float4(0.f, 0.f, 0.f, 0.f);
    for (int i = gid; i < n4; i += gridDim.x * blockDim.x) out[i] = z;
}

// ---------------------------------------------------------------------------
// K1: routing + x fp16 conversion fused (one warp/token)
// ---------------------------------------------------------------------------
__global__ void route_kernel(const float4* __restrict__ x4,
                             const float* __restrict__ Wg) {
    int warp = (blockIdx.x * blockDim.x + threadIdx.x) >> 5;
    int lane = threadIdx.x & 31;
    if (warp >= NTOK) return;

    float sc[NE];
#pragma unroll
    for (int e = 0; e < NE; e++) sc[e] = 0.f;

#pragma unroll
    for (int j = 0; j < 8; j++) {
        int i4 = j * 32 + lane;
        float4 xv = x4[(size_t)warp * (DIM / 4) + i4];
        *(uint2*)(g_x + (size_t)warp * DIM + i4 * 4) = cvt4h(xv);
        float xs[4] = {xv.x, xv.y, xv.z, xv.w};
#pragma unroll
        for (int c = 0; c < 4; c++) {
            int row = i4 * 4 + c;
#pragma unroll
            for (int e = 0; e < NE; e++)
                sc[e] += xs[c] * Wg[row * NE + e];
        }
    }
#pragma unroll
    for (int o = 16; o > 0; o >>= 1)
#pragma unroll
        for (int e = 0; e < NE; e++)
            sc[e] += __shfl_xor_sync(0xffffffffu, sc[e], o);

    if (lane == 0) {
        int i0 = 0; float s0 = sc[0];
#pragma unroll
        for (int e = 1; e < NE; e++) if (sc[e] > s0) { s0 = sc[e]; i0 = e; }
        int i1 = -1; float s1 = -INFINITY;
#pragma unroll
        for (int e = 0; e < NE; e++)
            if (e != i0 && sc[e] > s1) { s1 = sc[e]; i1 = e; }
        float e1  = expf(s1 - s0);
        float inv = 1.f / (1.f + e1);
        int p0 = atomicAdd(&g_counts[i0], 1);
        g_tok[i0 * NTOK + p0] = warp;
        g_wt [i0 * NTOK + p0] = inv;
        int p1 = atomicAdd(&g_counts[i1], 1);
        g_tok[i1 * NTOK + p1] = warp;
        g_wt [i1 * NTOK + p1] = e1 * inv;
    }
}

__device__ __forceinline__ int expert_base(int e) {
    int b = 0;
#pragma unroll
    for (int j = 0; j < NE; j++) if (j < e) b += g_counts[j];
    return b;
}

// ---------------------------------------------------------------------------
// K3: FFN1 — fp16 single-pass, BK=64. BM=128, BN=64, 256 thr (8 warps 4m x 2n,
// warp tile 32x32). Stage 32KB x3 = 96KB; 2 CTAs/SM.  [R10 measured-best]
// Loop: wait(1) -> barrier -> mma(it, 4 ks) -> load(it+2) -> commit.
// ---------------------------------------------------------------------------
#define F1_STAGE 32768
#define F2_STAGE 24576

__global__ __launch_bounds__(256, 2) void ffn1_kernel() {
    extern __shared__ char sm[];
    __shared__ int s_tok[128];

    int e   = blockIdx.z;
    int cnt = g_counts[e];
    int m0  = blockIdx.y * 128;
    if (m0 >= cnt) return;
    int n0   = blockIdx.x * 64;
    int base = expert_base(e);

    int tid = threadIdx.x, wid = tid >> 5, l = tid & 31;
    int mw = (wid >> 1) * 32, nw = (wid & 1) * 32;

    if (tid < 128) {
        int mg = m0 + tid;
        s_tok[tid] = (mg < cnt) ? g_tok[e * NTOK + mg] : -1;
    }
    __syncthreads();

    uint32_t sbase = smem_to_u32(sm);
    size_t eoffW = (size_t)e * DIM * HID;

    auto load_tile = [&](int it, int b) {
        int kb = it * 64;
        uint32_t abase = sbase + b * F1_STAGE;
        uint32_t bbase = abase + 16384;
        // A: 1024 chunks of 16B (128 rows x 8)
#pragma unroll
        for (int j = 0; j < 4; j++) {
            int c = tid + j * 256;
            int row = c >> 3, cc = c & 7;
            int tok = s_tok[row];
            const void* src = g_x + ((size_t)(tok < 0 ? 0 : tok) * DIM + kb + cc * 8);
            uint32_t dst = abase + SWZ((uint32_t)(row * 128 + cc * 16));
            int sz = (tok < 0) ? 0 : 16;
            CP_ASYNC(dst, src, sz);
        }
        // B: 1024 chunks over 2 planes (W1, W3), 64k x 64n each
#pragma unroll
        for (int j = 0; j < 4; j++) {
            int c = tid + j * 256;
            int p = c >> 9, w = c & 511;
            int kr = w >> 3, n = (w & 7) * 8;
            const __half* sp = p ? g_w3 : g_w1;
            const void* src = sp + (eoffW + (size_t)(kb + kr) * HID + n0 + n);
            uint32_t dst = bbase + p * 8192 + SWZ((uint32_t)(kr * 128 + n * 2));
            CP_ASYNC(dst, src, 16);
        }
    };

    float acc1[2][4][4] = {};
    float acc3[2][4][4] = {};

    const int NIT = DIM / 64;
    load_tile(0, 0); CP_COMMIT();
    load_tile(1, 1); CP_COMMIT();

    for (int it = 0; it < NIT; it++) {
        CP_WAIT(1);
        __syncthreads();

        uint32_t aB = sbase + (it % 3) * F1_STAGE;
        uint32_t bB = aB + 16384;
        uint32_t b1 = bB, b3 = bB + 8192;

#pragma unroll
        for (int ks = 0; ks < 4; ks++) {
            uint32_t a[2][4];
#pragma unroll
            for (int mt = 0; mt < 2; mt++) {
                int row  = mw + mt * 16 + ((l >> 3) & 1) * 8 + (l & 7);
                int kbyt = ks * 32 + (l >> 4) * 16;
                ldsm_x4(aB + SWZ((uint32_t)(row * 128 + kbyt)), a[mt]);
            }
            int krow = ks * 16 + ((l >> 3) & 1) * 8 + (l & 7);
            uint32_t rb0 = krow * 128 + (nw + (l >> 4) * 8) * 2;
            uint32_t rb1 = rb0 + 32;
            uint32_t s0 = SWZ(rb0), s1 = SWZ(rb1);

            {   // W1
                uint32_t bh[8];
                ldsm_x4_t(b1 + s0, bh); ldsm_x4_t(b1 + s1, bh + 4);
#pragma unroll
                for (int mt = 0; mt < 2; mt++)
#pragma unroll
                    for (int nj = 0; nj < 4; nj++)
                        mma_f16(acc1[mt][nj], a[mt], &bh[nj * 2]);
            }
            {   // W3
                uint32_t bh[8];
                ldsm_x4_t(b3 + s0, bh); ldsm_x4_t(b3 + s1, bh + 4);
#pragma unroll
                for (int mt = 0; mt < 2; mt++)
#pragma unroll
                    for (int nj = 0; nj < 4; nj++)
                        mma_f16(acc3[mt][nj], a[mt], &bh[nj * 2]);
            }
        }

        if (it + 2 < NIT) load_tile(it + 2, (it + 2) % 3);
        CP_COMMIT();
    }

    // ---- epilogue: SwiGLU -> g_h (fp16) ----
#pragma unroll
    for (int mt = 0; mt < 2; mt++) {
#pragma unroll
        for (int hf = 0; hf < 2; hf++) {
            int row = m0 + mw + mt * 16 + (l >> 2) + hf * 8;
            if (row < cnt) {
                size_t rb = (size_t)(base + row) * HID + n0 + nw;
#pragma unroll
                for (int nj = 0; nj < 4; nj++) {
                    float a0 = acc1[mt][nj][hf * 2 + 0];
                    float a1 = acc1[mt][nj][hf * 2 + 1];
                    float h0 = a0 / (1.f + __expf(-a0)) * acc3[mt][nj][hf * 2 + 0];
                    float h1 = a1 / (1.f + __expf(-a1)) * acc3[mt][nj][hf * 2 + 1];
                    int c = nj * 8 + (l & 3) * 2;
                    *(uint32_t*)(g_h + rb + c) =
                        pack2(__float2half_rn(h0), __float2half_rn(h1));
                }
            }
        }
    }
}

// ---------------------------------------------------------------------------
// K4: FFN2 — fp16 single-pass, BK=64. BM=128, BN=64, 128 thr (4 warps 2m x 2n,
// warp tile 64x32). Stage 24KB x3 = 72KB; 3 CTAs/SM.  [R11 measured-best]
// ---------------------------------------------------------------------------
__global__ __launch_bounds__(128, 3) void ffn2_kernel(float* __restrict__ out) {
    extern __shared__ char sm[];

    int e   = blockIdx.z;
    int cnt = g_counts[e];
    int m0  = blockIdx.y * 128;
    if (m0 >= cnt) return;
    int n0   = blockIdx.x * 64;
    int base = expert_base(e);

    int tid = threadIdx.x, wid = tid >> 5, l = tid & 31;
    int mw = (wid >> 1) * 64, nw = (wid & 1) * 32;

    uint32_t sbase = smem_to_u32(sm);
    size_t eoffW = (size_t)e * HID * DIM;

    auto load_tile = [&](int it, int b) {
        int kb = it * 64;
        uint32_t abase = sbase + b * F2_STAGE;
        uint32_t bbase = abase + 16384;
#pragma unroll
        for (int j = 0; j < 8; j++) {
            int c = tid + j * 128;
            int row = c >> 3, cc = c & 7;
            int mg = m0 + row;
            bool v = mg < cnt;
            const void* src = g_h + ((size_t)(v ? base + mg : 0) * HID + kb + cc * 8);
            uint32_t dst = abase + SWZ((uint32_t)(row * 128 + cc * 16));
            int sz = v ? 16 : 0;
            CP_ASYNC(dst, src, sz);
        }
#pragma unroll
        for (int j = 0; j < 4; j++) {
            int c = tid + j * 128;
            int kr = c >> 3, n = (c & 7) * 8;
            const void* src = g_w2 + (eoffW + (size_t)(kb + kr) * DIM + n0 + n);
            uint32_t dst = bbase + SWZ((uint32_t)(kr * 128 + n * 2));
            CP_ASYNC(dst, src, 16);
        }
    };

    float acc[4][4][4] = {};

    const int NIT = HID / 64;
    load_tile(0, 0); CP_COMMIT();
    load_tile(1, 1); CP_COMMIT();

    for (int it = 0; it < NIT; it++) {
        CP_WAIT(1);
        __syncthreads();

        uint32_t aB = sbase + (it % 3) * F2_STAGE;
        uint32_t bB = aB + 16384;

#pragma unroll
        for (int ks = 0; ks < 4; ks++) {
            uint32_t a[4][4];
#pragma unroll
            for (int mt = 0; mt < 4; mt++) {
                int row  = mw + mt * 16 + ((l >> 3) & 1) * 8 + (l & 7);
                int kbyt = ks * 32 + (l >> 4) * 16;
                ldsm_x4(aB + SWZ((uint32_t)(row * 128 + kbyt)), a[mt]);
            }
            int krow = ks * 16 + ((l >> 3) & 1) * 8 + (l & 7);
            uint32_t rb0 = krow * 128 + (nw + (l >> 4) * 8) * 2;
            uint32_t rb1 = rb0 + 32;
            uint32_t s0 = SWZ(rb0), s1 = SWZ(rb1);

            uint32_t bh[8];
            ldsm_x4_t(bB + s0, bh); ldsm_x4_t(bB + s1, bh + 4);
#pragma unroll
            for (int mt = 0; mt < 4; mt++)
#pragma unroll
                for (int nj = 0; nj < 4; nj++)
                    mma_f16(acc[mt][nj], a[mt], &bh[nj * 2]);
        }

        if (it + 2 < NIT) load_tile(it + 2, (it + 2) % 3);
        CP_COMMIT();
    }

    // ---- epilogue: out[tok] += w * acc ----
#pragma unroll
    for (int mt = 0; mt < 4; mt++) {
#pragma unroll
        for (int hf = 0; hf < 2; hf++) {
            int row = m0 + mw + mt * 16 + (l >> 2) + hf * 8;
            if (row < cnt) {
                int   tok = g_tok[e * NTOK + row];
                float w   = g_wt [e * NTOK + row];
                float* orow = out + (size_t)tok * DIM + n0 + nw;
#pragma unroll
                for (int nj = 0; nj < 4; nj++) {
                    int c = nj * 8 + (l & 3) * 2;
                    atomicAdd(&orow[c],     w * acc[mt][nj][hf * 2 + 0]);
                    atomicAdd(&orow[c + 1], w * acc[mt][nj][hf * 2 + 1]);
                }
            }
        }
    }
}

// ---------------------------------------------------------------------------
// Launch
// ---------------------------------------------------------------------------
extern "C" void kernel_launch(void* const* d_in, const int* in_sizes, int n_in,
                              void* d_out, int out_size) {
    const float* x  = (const float*)d_in[0];
    const float* Wg = (const float*)d_in[1];
    const float* W1 = (const float*)d_in[2];
    const float* W3 = (const float*)d_in[3];
    const float* W2 = (const float*)d_in[4];
    float* out = (float*)d_out;

    cudaFuncSetAttribute(ffn1_kernel,
        cudaFuncAttributeMaxDynamicSharedMemorySize, 3 * F1_STAGE);
    cudaFuncSetAttribute(ffn2_kernel,
        cudaFuncAttributeMaxDynamicSharedMemorySize, 3 * F2_STAGE);

    prep_kernel<<<3 * 1024, 512>>>((const float4*)W1, (const float4*)W3,
                                   (const float4*)W2, (float4*)out,
                                   out_size / 4);
    route_kernel<<<NTOK / 8, 256>>>((const float4*)x, Wg);

    dim3 g1(HID / 64, NTOK / 128, NE);    // 32 x 32 x 8
    ffn1_kernel<<<g1, 256, 3 * F1_STAGE>>>();

    dim3 g2(DIM / 64, NTOK / 128, NE);    // 16 x 32 x 8
    ffn2_kernel<<<g2, 128, 3 * F2_STAGE>>>(out);
}